// round 13
// baseline (speedup 1.0000x reference)
#include <cuda_runtime.h>
#include <cuda_fp16.h>
#include <cstdint>

#define BDIM 64
#define TDIM 512
#define IDIM 1024
#define HDIM 1024
#define BT   (BDIM * TDIM)      // 32768

#define BM 128                  // M tile (rows m' = t*B+b)
#define BN3 192                 // 3 gates x 64
#define BK 32                   // K per chunk (halves)
#define NCH (IDIM / BK)         // 32 chunks
#define RP 40                   // smem row pitch in halves (80B, conflict-free mod 32 banks)
#define A_H (BM * RP)           // 5120 halves per A stage
#define B_H (BN3 * RP)          // 7680 halves per B stage
#define STG_B ((A_H + B_H) * 2) // 25600 bytes per stage
#define NST 4
#define SMEM_DYN (NST * STG_B)  // 102400 -> 2 CTAs/SM

// ---------------- scratch ----------------
__device__ __half g_xh[(size_t)BT * IDIM];          // fp16 x, remapped m' = t*B+b
__device__ __half g_wh[(size_t)3 * HDIM * IDIM];    // fp16 W packed [nt][3*64][IDIM]
__device__ float  g_hr[3][BDIM * HDIM];             // h0@R.T + b + rb per gate

// ---------------- helpers ----------------
__device__ __forceinline__ uint32_t smem_u32(const void* p) {
    uint32_t a;
    asm("{ .reg .u64 t; cvta.to.shared.u64 t, %1; cvt.u32.u64 %0, t; }" : "=r"(a) : "l"(p));
    return a;
}
#define LDMX4(r, addr) \
    asm volatile("ldmatrix.sync.aligned.m8n8.x4.shared.b16 {%0,%1,%2,%3}, [%4];\n" \
        : "=r"((r)[0]), "=r"((r)[1]), "=r"((r)[2]), "=r"((r)[3]) : "r"(addr))

__device__ __forceinline__ void mma16816(float* c, const uint32_t* a, const uint32_t* b) {
    asm volatile(
        "mma.sync.aligned.m16n8k16.row.col.f32.f16.f16.f32 "
        "{%0,%1,%2,%3}, {%4,%5,%6,%7}, {%8,%9}, {%0,%1,%2,%3};\n"
        : "+f"(c[0]), "+f"(c[1]), "+f"(c[2]), "+f"(c[3])
        : "r"(a[0]), "r"(a[1]), "r"(a[2]), "r"(a[3]), "r"(b[0]), "r"(b[1]));
}

__device__ __forceinline__ float sigmoid_f(float x) { return 1.f / (1.f + __expf(-x)); }
__device__ __forceinline__ float tanh_f(float x)    { return 2.f / (1.f + __expf(-2.f * x)) - 1.f; }

// ---------------- conversion kernels ----------------
// g_xh[m'][k] = fp16(x[b][t][k]),  m' = t*B + b
__global__ void conv_x(const float* __restrict__ x) {
    size_t i = (size_t)blockIdx.x * blockDim.x + threadIdx.x;  // 8-half group
    int m = (int)(i >> 7);
    int c8 = (int)(i & 127) * 8;
    int b = m & 63, t = m >> 6;
    const float4* s = (const float4*)(x + ((size_t)b * TDIM + t) * IDIM + c8);
    float4 v0 = s[0], v1 = s[1];
    union { __half2 h[4]; uint4 u; } r;
    r.h[0] = __floats2half2_rn(v0.x, v0.y);
    r.h[1] = __floats2half2_rn(v0.z, v0.w);
    r.h[2] = __floats2half2_rn(v1.x, v1.y);
    r.h[3] = __floats2half2_rn(v1.z, v1.w);
    *(uint4*)(g_xh + (size_t)m * IDIM + c8) = r.u;
}

// packed weights: prow = nt*192 + g*64 + (h&63) for h = nt*64 + (h&63)
__global__ void conv_w(const float* __restrict__ Wf,
                       const float* __restrict__ Wi,
                       const float* __restrict__ Wg) {
    size_t i = (size_t)blockIdx.x * blockDim.x + threadIdx.x;  // 8-half group
    int prow = (int)(i >> 7);
    int c8 = (int)(i & 127) * 8;
    int nt = prow / BN3, r = prow % BN3;
    int g = r >> 6, hl = r & 63;
    int h = nt * 64 + hl;
    const float* W = (g == 0) ? Wf : ((g == 1) ? Wi : Wg);
    const float4* s = (const float4*)(W + (size_t)h * IDIM + c8);
    float4 v0 = s[0], v1 = s[1];
    union { __half2 h2[4]; uint4 u; } rr;
    rr.h2[0] = __floats2half2_rn(v0.x, v0.y);
    rr.h2[1] = __floats2half2_rn(v0.z, v0.w);
    rr.h2[2] = __floats2half2_rn(v1.x, v1.y);
    rr.h2[3] = __floats2half2_rn(v1.z, v1.w);
    *(uint4*)(g_wh + (size_t)prow * IDIM + c8) = rr.u;
}

// ---------------- recurrent part (fp32) ----------------
__global__ void hr_kernel(const float* __restrict__ h0,
                          const float* __restrict__ Rf, const float* __restrict__ bf, const float* __restrict__ rbf,
                          const float* __restrict__ Ri, const float* __restrict__ bi, const float* __restrict__ rbi,
                          const float* __restrict__ Rg, const float* __restrict__ bg, const float* __restrict__ rbg) {
    int w = blockIdx.x * (blockDim.x >> 5) + (threadIdx.x >> 5);
    int lane = threadIdx.x & 31;
    int g = w >> 16;
    int rem = w & 65535;
    int b = rem >> 10;
    int h = rem & 1023;
    const float* R; const float* bb; const float* rb;
    if (g == 0)      { R = Rf; bb = bf; rb = rbf; }
    else if (g == 1) { R = Ri; bb = bi; rb = rbi; }
    else             { R = Rg; bb = bg; rb = rbg; }

    const float4* h4 = (const float4*)(h0 + (size_t)b * HDIM);
    const float4* R4 = (const float4*)(R + (size_t)h * HDIM);
    float s = 0.f;
    #pragma unroll
    for (int k = lane; k < HDIM / 4; k += 32) {
        float4 a = h4[k], r = R4[k];
        s += a.x * r.x + a.y * r.y + a.z * r.z + a.w * r.w;
    }
    #pragma unroll
    for (int off = 16; off; off >>= 1) s += __shfl_xor_sync(0xffffffffu, s, off);
    if (lane == 0) g_hr[g][rem] = s + bb[h] + rb[h];
}

// ---------------- fused 3-gate FP16 GEMM + LSTM epilogue ----------------
// 8 warps = 4(m) x 2(n); warp tile m32 x n32 per gate; 2 CTAs/SM.
// Odd warps traverse ks and gates in reverse order to de-phase LDSM/MMA bursts.
__global__ __launch_bounds__(256, 2)
void lstm_fused(const float* __restrict__ c0, float* __restrict__ out, int write_last) {
    extern __shared__ char dsm[];
    const uint32_t base = smem_u32(dsm);

    const int tid = threadIdx.x, lane = tid & 31, warp = tid >> 5;
    const int wodd = warp & 1;            // stagger parity
    const int wm = (warp & 3) * 32;       // warp m offset in 128
    const int wn = (warp >> 2) * 32;      // warp n offset in 64 (per gate)
    const int nt = blockIdx.x;            // 0..15 (h block of 64)
    const int m0 = blockIdx.y * BM;       // m' offset
    const int n0 = nt * 64;

    // cp.async mapping: 16B granules; per row 32 halves = 4 granules
    const int cr = tid >> 2;              // row 0..63
    const int cg = (tid & 3) * 8;         // half col within chunk
    const __half* gA = g_xh + (size_t)(m0 + cr) * IDIM + cg;
    const __half* gB = g_wh + (size_t)(nt * BN3 + cr) * IDIM + cg;
    const uint32_t sA = base + (uint32_t)(cr * RP + cg) * 2;
    const uint32_t sB = base + (uint32_t)(A_H + cr * RP + cg) * 2;

    float acc[3][2][4][4];
    #pragma unroll
    for (int g = 0; g < 3; g++)
        #pragma unroll
        for (int mt = 0; mt < 2; mt++)
            #pragma unroll
            for (int j = 0; j < 4; j++)
                #pragma unroll
                for (int v = 0; v < 4; v++) acc[g][mt][j][v] = 0.f;

    auto load_stage = [&](int stage, int ch) {
        const uint32_t off = stage * STG_B;
        const __half* a = gA + ch * BK;
        const __half* b = gB + ch * BK;
        #pragma unroll
        for (int i = 0; i < 2; i++)
            asm volatile("cp.async.cg.shared.global [%0], [%1], 16;\n"
                         :: "r"(sA + off + i * 64 * RP * 2), "l"(a + (size_t)i * 64 * IDIM));
        #pragma unroll
        for (int i = 0; i < 3; i++)
            asm volatile("cp.async.cg.shared.global [%0], [%1], 16;\n"
                         :: "r"(sB + off + i * 64 * RP * 2), "l"(b + (size_t)i * 64 * IDIM));
        asm volatile("cp.async.commit_group;\n");
    };

    load_stage(0, 0);
    load_stage(1, 1);
    load_stage(2, 2);

    // ldmatrix lane offsets
    const int a_row = lane & 15;
    const int a_k8  = (lane >> 4) * 8;                    // halves
    const int b_row = (lane & 7) + ((lane >> 4) << 3);    // n within 16
    const int b_k8  = ((lane >> 3) & 1) * 8;              // halves

    for (int kt = 0; kt < NCH; kt++) {
        asm volatile("cp.async.wait_group %0;\n" :: "n"(NST - 2));
        __syncthreads();
        const int cur = kt % NST;
        if (kt + 3 < NCH) load_stage((kt + 3) % NST, kt + 3);

        const uint32_t aB = base + cur * STG_B;
        const uint32_t bB = aB + A_H * 2;

        #pragma unroll
        for (int kss = 0; kss < BK / 16; kss++) {
            const int ks = wodd ? (BK / 16 - 1 - kss) : kss;   // ks stagger
            uint32_t afr[2][4];
            #pragma unroll
            for (int mt = 0; mt < 2; mt++)
                LDMX4(afr[mt], aB + (uint32_t)((wm + mt * 16 + a_row) * RP + ks * 16 + a_k8) * 2);

            uint32_t bfr[2][4][2];
            // preload first gate in this warp's traversal order
            {
                const int gfirst = wodd ? 2 : 0;
                #pragma unroll
                for (int nt2 = 0; nt2 < 2; nt2++) {
                    uint32_t r[4];
                    LDMX4(r, bB + (uint32_t)((gfirst * 64 + wn + nt2 * 16 + b_row) * RP + ks * 16 + b_k8) * 2);
                    bfr[0][nt2 * 2][0] = r[0]; bfr[0][nt2 * 2][1] = r[1];
                    bfr[0][nt2 * 2 + 1][0] = r[2]; bfr[0][nt2 * 2 + 1][1] = r[3];
                }
            }
            #pragma unroll
            for (int gg = 0; gg < 3; gg++) {
                const int g = wodd ? (2 - gg) : gg;           // gate stagger
                if (gg < 2) {
                    const int gnext = wodd ? (1 - gg) : (gg + 1);
                    #pragma unroll
                    for (int nt2 = 0; nt2 < 2; nt2++) {
                        uint32_t r[4];
                        LDMX4(r, bB + (uint32_t)((gnext * 64 + wn + nt2 * 16 + b_row) * RP + ks * 16 + b_k8) * 2);
                        bfr[(gg + 1) & 1][nt2 * 2][0] = r[0]; bfr[(gg + 1) & 1][nt2 * 2][1] = r[1];
                        bfr[(gg + 1) & 1][nt2 * 2 + 1][0] = r[2]; bfr[(gg + 1) & 1][nt2 * 2 + 1][1] = r[3];
                    }
                }
                #pragma unroll
                for (int mt = 0; mt < 2; mt++)
                    #pragma unroll
                    for (int j = 0; j < 4; j++)
                        mma16816(acc[g][mt][j], afr[mt], bfr[gg & 1][j]);
            }
        }
    }
    __syncthreads();   // done with smem tiles; reuse for transpose staging

    // ---- epilogue: gates + cell + tanh, staged transpose ----
    float* trans = (float*)dsm;          // [64 h][132 m]
    float* hlast = out + (size_t)HDIM * BT;
    float* clast = hlast + (size_t)BDIM * HDIM;
    const int grp = lane >> 2, tig = lane & 3;

    #pragma unroll
    for (int mt = 0; mt < 2; mt++) {
        #pragma unroll
        for (int j = 0; j < 4; j++) {
            #pragma unroll
            for (int v = 0; v < 4; v++) {
                const int m_l = wm + mt * 16 + grp + ((v >> 1) << 3);
                const int h_l = wn + j * 8 + tig * 2 + (v & 1);
                const int mg = m0 + m_l;
                const int b = mg & 63, t = mg >> 6;
                const int h = n0 + h_l;
                const int bh = (b << 10) + h;
                const float pf = acc[0][mt][j][v] + g_hr[0][bh];
                const float pi = acc[1][mt][j][v] + g_hr[1][bh];
                const float pg = acc[2][mt][j][v] + g_hr[2][bh];
                const float f  = sigmoid_f(pf);
                const float ii = sigmoid_f(pi);
                const float gg = tanh_f(pg);
                const float cv = f * c0[bh] + ii * gg;
                const float hh = tanh_f(cv);
                trans[h_l * 132 + m_l] = hh;
                if (write_last && t == TDIM - 1) { hlast[bh] = hh; clast[bh] = cv; }
            }
        }
    }
    __syncthreads();
    // vectorized writeback: 64 rows x 128 cols, float4 per thread-step
    #pragma unroll
    for (int idx = tid; idx < 64 * 32; idx += 256) {
        const int h = idx >> 5, m4 = (idx & 31) * 4;
        const float* tr = &trans[h * 132 + m4];
        float4 v = make_float4(tr[0], tr[1], tr[2], tr[3]);
        *(float4*)&out[(size_t)(n0 + h) * BT + (m0 + m4)] = v;
    }
}

// ---------------- launch ----------------
extern "C" void kernel_launch(void* const* d_in, const int* in_sizes, int n_in,
                              void* d_out, int out_size) {
    const float* x   = (const float*)d_in[0];
    const float* h0  = (const float*)d_in[1];
    const float* c0  = (const float*)d_in[2];
    const float* Wf  = (const float*)d_in[3];
    const float* bf  = (const float*)d_in[4];
    const float* Rf  = (const float*)d_in[5];
    const float* rbf = (const float*)d_in[6];
    const float* Wi  = (const float*)d_in[7];
    const float* bi  = (const float*)d_in[8];
    const float* Ri  = (const float*)d_in[9];
    const float* rbi = (const float*)d_in[10];
    const float* Wg  = (const float*)d_in[11];
    const float* bg  = (const float*)d_in[12];
    const float* Rg  = (const float*)d_in[13];
    const float* rbg = (const float*)d_in[14];
    float* out = (float*)d_out;

    cudaFuncSetAttribute(lstm_fused, cudaFuncAttributeMaxDynamicSharedMemorySize, SMEM_DYN);

    // convert inputs to fp16 (x remapped to m'=t*B+b; W packed per n-tile)
    conv_x<<<(int)(((size_t)BT * IDIM / 8) / 256), 256>>>(x);
    conv_w<<<(int)(((size_t)3 * HDIM * IDIM / 8) / 256), 256>>>(Wf, Wi, Wg);

    // recurrent contribution (+ biases), fp32
    hr_kernel<<<(3 * BDIM * HDIM) / 8, 256>>>(h0, Rf, bf, rbf, Ri, bi, rbi, Rg, bg, rbg);

    // fused 3-gate GEMM + epilogue
    const long long need = (long long)HDIM * BT + 2LL * BDIM * HDIM;
    int write_last = ((long long)out_size >= need) ? 1 : 0;
    dim3 grid(HDIM / 64, BT / BM);   // (16, 256); x-fast => A tile reused across n-blocks in L2
    lstm_fused<<<grid, 256, SMEM_DYN>>>(c0, out, write_last);
}

// round 14
// speedup vs baseline: 6.0274x; 6.0274x over previous
#include <cuda_runtime.h>
#include <cuda_fp16.h>
#include <cstdint>

#define BDIM 64
#define TDIM 512
#define IDIM 1024
#define HDIM 1024
#define BT   (BDIM * TDIM)      // 32768

#define BM 128                  // M tile (rows m' = t*B+b)
#define BN3 192                 // 3 gates x 64
#define BK 32                   // K per chunk (halves) -> 64B per row
#define NCH (IDIM / BK)         // 32 chunks
#define A_BYTES (BM * BK * 2)   // 8192
#define B_BYTES (BN3 * BK * 2)  // 12288
#define STG_B (A_BYTES + B_BYTES) // 20480 per stage
#define NST 4
#define SMEM_DYN (NST * STG_B)  // 81920 -> 2 CTAs/SM

// ---------------- scratch (k-chunk-major, 16B-chunk swizzled) ----------------
// layout: [kt][row][chunk c'], c' = c ^ ((row>>1)&3), chunk = 16B (8 halves)
__device__ __half g_xh[(size_t)BT * IDIM];          // A: rows = m' = t*B+b
__device__ __half g_wh[(size_t)3 * HDIM * IDIM];    // B: rows = nt*192 + g*64 + h%64
__device__ float  g_hr[3][BDIM * HDIM];             // h0@R.T + b + rb per gate

// ---------------- helpers ----------------
__device__ __forceinline__ uint32_t smem_u32(const void* p) {
    uint32_t a;
    asm("{ .reg .u64 t; cvta.to.shared.u64 t, %1; cvt.u32.u64 %0, t; }" : "=r"(a) : "l"(p));
    return a;
}
#define LDMX4(r, addr) \
    asm volatile("ldmatrix.sync.aligned.m8n8.x4.shared.b16 {%0,%1,%2,%3}, [%4];\n" \
        : "=r"((r)[0]), "=r"((r)[1]), "=r"((r)[2]), "=r"((r)[3]) : "r"(addr))

__device__ __forceinline__ void mma16816(float* c, const uint32_t* a, const uint32_t* b) {
    asm volatile(
        "mma.sync.aligned.m16n8k16.row.col.f32.f16.f16.f32 "
        "{%0,%1,%2,%3}, {%4,%5,%6,%7}, {%8,%9}, {%0,%1,%2,%3};\n"
        : "+f"(c[0]), "+f"(c[1]), "+f"(c[2]), "+f"(c[3])
        : "r"(a[0]), "r"(a[1]), "r"(a[2]), "r"(a[3]), "r"(b[0]), "r"(b[1]));
}

#define MBARRIER_INIT(addr, count) \
    asm volatile("mbarrier.init.shared.b64 [%0], %1;" :: "r"((uint32_t)(addr)), "r"((uint32_t)(count)) : "memory")
#define MBARRIER_EXPECT_TX(addr, bytes) \
    asm volatile("mbarrier.arrive.expect_tx.shared.b64 _, [%0], %1;" :: "r"((uint32_t)(addr)), "r"((uint32_t)(bytes)) : "memory")
#define MBARRIER_ARRIVE(addr) \
    asm volatile("mbarrier.arrive.shared.b64 _, [%0];" :: "r"((uint32_t)(addr)) : "memory")
#define MBARRIER_INVAL(addr) \
    asm volatile("mbarrier.inval.shared.b64 [%0];" :: "r"((uint32_t)(addr)) : "memory")

#define MBARRIER_WAIT_ACQ(mbar, par) do { \
    uint32_t _m = (uint32_t)(mbar); uint32_t _p = (uint32_t)(par); uint32_t _d; \
    asm volatile("{ .reg .pred p; mbarrier.try_wait.parity.acquire.cta.shared::cta.b64 p, [%1], %2; selp.b32 %0, 1, 0, p; }" \
        : "=r"(_d) : "r"(_m), "r"(_p) : "memory"); \
    if (!_d) { \
        asm volatile("{ .reg .pred P1; WL_%=: mbarrier.try_wait.parity.acquire.cta.shared::cta.b64 P1, [%0], %1, 0x989680; @P1 bra.uni WD_%=; bra.uni WL_%=; WD_%=: }" \
            :: "r"(_m), "r"(_p) : "memory"); \
    } } while (0)

#define MBARRIER_WAIT_RLX(mbar, par) do { \
    uint32_t _m = (uint32_t)(mbar); uint32_t _p = (uint32_t)(par); uint32_t _d; \
    asm volatile("{ .reg .pred p; mbarrier.try_wait.parity.relaxed.cta.shared::cta.b64 p, [%1], %2, 0x989680; selp.b32 %0, 1, 0, p; }" \
        : "=r"(_d) : "r"(_m), "r"(_p) : "memory"); \
    if (!_d) { \
        asm volatile("{ .reg .pred P1; WL_%=: mbarrier.try_wait.parity.relaxed.cta.shared::cta.b64 P1, [%0], %1, 0x989680; @P1 bra.uni WD_%=; bra.uni WL_%=; WD_%=: }" \
            :: "r"(_m), "r"(_p) : "memory"); \
    } } while (0)

#define CP_BULK(dst, src, bytes, mbar) \
    asm volatile("cp.async.bulk.shared::cta.global.mbarrier::complete_tx::bytes [%0], [%1], %2, [%3];" \
        :: "r"((uint32_t)(dst)), "l"(src), "r"((uint32_t)(bytes)), "r"((uint32_t)(mbar)) : "memory")

__device__ __forceinline__ float sigmoid_f(float x) { return 1.f / (1.f + __expf(-x)); }
__device__ __forceinline__ float tanh_f(float x)    { return 2.f / (1.f + __expf(-2.f * x)) - 1.f; }

// ---------------- conversion kernels (k-chunk-major + swizzle) ----------------
// granule = 16B (8 halves). g_xh granule index: (kt*BT + m)*4 + (c ^ ((m>>1)&3))
__global__ void conv_x(const float* __restrict__ x) {
    size_t i = (size_t)blockIdx.x * blockDim.x + threadIdx.x;
    int kt = (int)(i >> 17);              // BT*4 = 131072
    int rem = (int)(i & 131071);
    int m = rem >> 2, c = rem & 3;
    int b = m & 63, t = m >> 6;
    const float4* s = (const float4*)(x + ((size_t)b * TDIM + t) * IDIM + kt * 32 + c * 8);
    float4 v0 = s[0], v1 = s[1];
    union { __half2 h[4]; uint4 u; } r;
    r.h[0] = __floats2half2_rn(v0.x, v0.y);
    r.h[1] = __floats2half2_rn(v0.z, v0.w);
    r.h[2] = __floats2half2_rn(v1.x, v1.y);
    r.h[3] = __floats2half2_rn(v1.z, v1.w);
    int cp = c ^ ((m >> 1) & 3);
    *(uint4*)(g_xh + (((size_t)kt * BT + m) * 4 + cp) * 8) = r.u;
}

// g_wh granule index: (kt*3072 + prow)*4 + (c ^ ((prow>>1)&3)); prow = nt*192 + g*64 + h%64
__global__ void conv_w(const float* __restrict__ Wf,
                       const float* __restrict__ Wi,
                       const float* __restrict__ Wg) {
    size_t i = (size_t)blockIdx.x * blockDim.x + threadIdx.x;
    int kt = (int)(i / 12288);
    int rem = (int)(i - (size_t)kt * 12288);
    int prow = rem >> 2, c = rem & 3;
    int nt = prow / 192, r = prow - nt * 192;
    int g = r >> 6, hl = r & 63;
    int h = nt * 64 + hl;
    const float* W = (g == 0) ? Wf : ((g == 1) ? Wi : Wg);
    const float4* s = (const float4*)(W + (size_t)h * IDIM + kt * 32 + c * 8);
    float4 v0 = s[0], v1 = s[1];
    union { __half2 h2[4]; uint4 u; } rr;
    rr.h2[0] = __floats2half2_rn(v0.x, v0.y);
    rr.h2[1] = __floats2half2_rn(v0.z, v0.w);
    rr.h2[2] = __floats2half2_rn(v1.x, v1.y);
    rr.h2[3] = __floats2half2_rn(v1.z, v1.w);
    int cp = c ^ ((prow >> 1) & 3);
    *(uint4*)(g_wh + (((size_t)kt * 3072 + prow) * 4 + cp) * 8) = rr.u;
}

// ---------------- recurrent part (fp32) ----------------
__global__ void hr_kernel(const float* __restrict__ h0,
                          const float* __restrict__ Rf, const float* __restrict__ bf, const float* __restrict__ rbf,
                          const float* __restrict__ Ri, const float* __restrict__ bi, const float* __restrict__ rbi,
                          const float* __restrict__ Rg, const float* __restrict__ bg, const float* __restrict__ rbg) {
    int w = blockIdx.x * (blockDim.x >> 5) + (threadIdx.x >> 5);
    int lane = threadIdx.x & 31;
    int g = w >> 16;
    int rem = w & 65535;
    int b = rem >> 10;
    int h = rem & 1023;
    const float* R; const float* bb; const float* rb;
    if (g == 0)      { R = Rf; bb = bf; rb = rbf; }
    else if (g == 1) { R = Ri; bb = bi; rb = rbi; }
    else             { R = Rg; bb = bg; rb = rbg; }

    const float4* h4 = (const float4*)(h0 + (size_t)b * HDIM);
    const float4* R4 = (const float4*)(R + (size_t)h * HDIM);
    float s = 0.f;
    #pragma unroll
    for (int k = lane; k < HDIM / 4; k += 32) {
        float4 a = h4[k], r = R4[k];
        s += a.x * r.x + a.y * r.y + a.z * r.z + a.w * r.w;
    }
    #pragma unroll
    for (int off = 16; off; off >>= 1) s += __shfl_xor_sync(0xffffffffu, s, off);
    if (lane == 0) g_hr[g][rem] = s + bb[h] + rb[h];
}

// ---------------- fused 3-gate FP16 GEMM + LSTM epilogue ----------------
// 8 warps = 4(m) x 2(n); warp tile m32 x n32 per gate; 2 CTAs/SM.
// mbarrier producer/consumer pipeline, NO __syncthreads in mainloop.
__global__ __launch_bounds__(256, 2)
void lstm_fused(const float* __restrict__ c0, float* __restrict__ out, int write_last) {
    extern __shared__ char dsm[];
    __shared__ __align__(16) uint64_t bars[8];   // full[0..3], empty[0..3]
    const uint32_t base = smem_u32(dsm);
    const uint32_t bfull = smem_u32(&bars[0]);
    const uint32_t bempty = smem_u32(&bars[4]);

    const int tid = threadIdx.x, lane = tid & 31, warp = tid >> 5;
    const int wm = (warp & 3) * 32;       // warp m offset in 128
    const int wn = (warp >> 2) * 32;      // warp n offset in 64 (per gate)
    const int nt = blockIdx.x;            // 0..15 (h block of 64)
    const int m0 = blockIdx.y * BM;       // m' offset
    const int n0 = nt * 64;

    // per-lane swizzled smem chunk offsets (16B chunks; c' = c ^ ((row>>1)&3))
    const int row_a = wm + (lane & 15);
    const int ca = (lane >> 4);                            // A chunk (ks=0)
    const uint32_t aoff = (uint32_t)(row_a * 4 + (ca ^ ((row_a >> 1) & 3))) * 16;
    const int row_b = wn + (lane & 7) + ((lane >> 4) << 3);
    const int cb = (lane >> 3) & 1;                        // B chunk (ks=0)
    const uint32_t boff = (uint32_t)(row_b * 4 + (cb ^ ((row_b >> 1) & 3))) * 16;

    if (tid == 0) {
        #pragma unroll
        for (int s = 0; s < NST; s++) { MBARRIER_INIT(bfull + 8 * s, 1); MBARRIER_INIT(bempty + 8 * s, 8); }
    }
    __syncthreads();

    // prologue: warps 0..3 each load one stage
    if (warp < NST && lane == 0) {
        const int s = warp;
        const uint32_t st = base + s * STG_B;
        MBARRIER_EXPECT_TX(bfull + 8 * s, STG_B);
        CP_BULK(st, (const char*)g_xh + ((size_t)s * BT + m0) * 64, A_BYTES, bfull + 8 * s);
        CP_BULK(st + A_BYTES, (const char*)g_wh + ((size_t)s * 3072 + nt * 192) * 64, B_BYTES, bfull + 8 * s);
    }

    float acc[3][2][4][4];
    #pragma unroll
    for (int g = 0; g < 3; g++)
        #pragma unroll
        for (int mt = 0; mt < 2; mt++)
            #pragma unroll
            for (int j = 0; j < 4; j++)
                #pragma unroll
                for (int v = 0; v < 4; v++) acc[g][mt][j][v] = 0.f;

    #pragma unroll 1
    for (int kt = 0; kt < NCH; kt++) {
        const int s = kt & 3;
        const uint32_t ph = (kt >> 2) & 1;
        const uint32_t aB = base + s * STG_B;
        const uint32_t bB = aB + A_BYTES;
        MBARRIER_WAIT_ACQ(bfull + 8 * s, ph);

        #pragma unroll
        for (int ks = 0; ks < 2; ks++) {
            const uint32_t kx = (uint32_t)(ks * 32);        // XOR flips chunk bit1
            uint32_t afr[2][4];
            LDMX4(afr[0], aB + ((aoff + 0)    ^ kx));
            LDMX4(afr[1], aB + ((aoff + 1024) ^ kx));

            uint32_t bfr[2][4][2];
            #pragma unroll
            for (int nt2 = 0; nt2 < 2; nt2++) {
                uint32_t r[4];
                LDMX4(r, bB + ((boff + 0 * 4096 + (uint32_t)nt2 * 1024) ^ kx));
                bfr[0][nt2 * 2][0] = r[0]; bfr[0][nt2 * 2][1] = r[1];
                bfr[0][nt2 * 2 + 1][0] = r[2]; bfr[0][nt2 * 2 + 1][1] = r[3];
            }
            #pragma unroll
            for (int g = 0; g < 3; g++) {
                if (g < 2) {
                    #pragma unroll
                    for (int nt2 = 0; nt2 < 2; nt2++) {
                        uint32_t r[4];
                        LDMX4(r, bB + ((boff + (uint32_t)(g + 1) * 4096 + (uint32_t)nt2 * 1024) ^ kx));
                        bfr[(g + 1) & 1][nt2 * 2][0] = r[0]; bfr[(g + 1) & 1][nt2 * 2][1] = r[1];
                        bfr[(g + 1) & 1][nt2 * 2 + 1][0] = r[2]; bfr[(g + 1) & 1][nt2 * 2 + 1][1] = r[3];
                    }
                }
                #pragma unroll
                for (int mt = 0; mt < 2; mt++)
                    #pragma unroll
                    for (int j = 0; j < 4; j++)
                        mma16816(acc[g][mt][j], afr[mt], bfr[g & 1][j]);
            }
        }

        __syncwarp();
        if (lane == 0) {
            MBARRIER_ARRIVE(bempty + 8 * s);
            const int nk = kt + 4;
            if (nk < NCH && (nk & 7) == warp) {
                // wait until all 8 warps consumed round kt of stage s, then refill
                MBARRIER_WAIT_RLX(bempty + 8 * s, ph);
                MBARRIER_EXPECT_TX(bfull + 8 * s, STG_B);
                CP_BULK(aB, (const char*)g_xh + ((size_t)nk * BT + m0) * 64, A_BYTES, bfull + 8 * s);
                CP_BULK(bB, (const char*)g_wh + ((size_t)nk * 3072 + nt * 192) * 64, B_BYTES, bfull + 8 * s);
            }
        }
    }

    __syncthreads();   // all consumption done; smem reusable for transpose
    if (tid == 0) {
        #pragma unroll
        for (int s = 0; s < 2 * NST; s++) MBARRIER_INVAL(smem_u32(&bars[s]));
    }

    // ---- epilogue: gates + cell + tanh, staged transpose ----
    float* trans = (float*)dsm;          // [64 h][132 m] = 33792B < 81920B
    float* hlast = out + (size_t)HDIM * BT;
    float* clast = hlast + (size_t)BDIM * HDIM;
    const int grp = lane >> 2, tig = lane & 3;

    #pragma unroll
    for (int mt = 0; mt < 2; mt++) {
        #pragma unroll
        for (int j = 0; j < 4; j++) {
            #pragma unroll
            for (int v = 0; v < 4; v++) {
                const int m_l = wm + mt * 16 + grp + ((v >> 1) << 3);
                const int h_l = wn + j * 8 + tig * 2 + (v & 1);
                const int mg = m0 + m_l;
                const int b = mg & 63, t = mg >> 6;
                const int h = n0 + h_l;
                const int bh = (b << 10) + h;
                const float pf = acc[0][mt][j][v] + g_hr[0][bh];
                const float pi = acc[1][mt][j][v] + g_hr[1][bh];
                const float pg = acc[2][mt][j][v] + g_hr[2][bh];
                const float f  = sigmoid_f(pf);
                const float ii = sigmoid_f(pi);
                const float gg = tanh_f(pg);
                const float cv = f * c0[bh] + ii * gg;
                const float hh = tanh_f(cv);
                trans[h_l * 132 + m_l] = hh;
                if (write_last && t == TDIM - 1) { hlast[bh] = hh; clast[bh] = cv; }
            }
        }
    }
    __syncthreads();
    // vectorized writeback: 64 rows x 128 cols, float4 per thread-step
    #pragma unroll
    for (int idx = tid; idx < 64 * 32; idx += 256) {
        const int h = idx >> 5, m4 = (idx & 31) * 4;
        const float* tr = &trans[h * 132 + m4];
        float4 v = make_float4(tr[0], tr[1], tr[2], tr[3]);
        *(float4*)&out[(size_t)(n0 + h) * BT + (m0 + m4)] = v;
    }
}

// ---------------- launch ----------------
extern "C" void kernel_launch(void* const* d_in, const int* in_sizes, int n_in,
                              void* d_out, int out_size) {
    const float* x   = (const float*)d_in[0];
    const float* h0  = (const float*)d_in[1];
    const float* c0  = (const float*)d_in[2];
    const float* Wf  = (const float*)d_in[3];
    const float* bf  = (const float*)d_in[4];
    const float* Rf  = (const float*)d_in[5];
    const float* rbf = (const float*)d_in[6];
    const float* Wi  = (const float*)d_in[7];
    const float* bi  = (const float*)d_in[8];
    const float* Ri  = (const float*)d_in[9];
    const float* rbi = (const float*)d_in[10];
    const float* Wg  = (const float*)d_in[11];
    const float* bg  = (const float*)d_in[12];
    const float* Rg  = (const float*)d_in[13];
    const float* rbg = (const float*)d_in[14];
    float* out = (float*)d_out;

    cudaFuncSetAttribute(lstm_fused, cudaFuncAttributeMaxDynamicSharedMemorySize, SMEM_DYN);

    // convert inputs to fp16 k-chunk-major swizzled layouts
    conv_x<<<(int)(((size_t)BT * IDIM / 8) / 256), 256>>>(x);
    conv_w<<<(int)(((size_t)3 * HDIM * IDIM / 8) / 256), 256>>>(Wf, Wi, Wg);

    // recurrent contribution (+ biases), fp32
    hr_kernel<<<(3 * BDIM * HDIM) / 8, 256>>>(h0, Rf, bf, rbf, Ri, bi, rbi, Rg, bg, rbg);

    // fused 3-gate GEMM + epilogue
    const long long need = (long long)HDIM * BT + 2LL * BDIM * HDIM;
    int write_last = ((long long)out_size >= need) ? 1 : 0;
    dim3 grid(HDIM / 64, BT / BM);   // (16, 256); x-fast => A tile reused across n-blocks in L2
    lstm_fused<<<grid, 256, SMEM_DYN>>>(c0, out, write_last);
}